// round 15
// baseline (speedup 1.0000x reference)
#include <cuda_runtime.h>
#include <math.h>

#define NXY 256
#define NT  24
#define NC  16
#define GRP 4      // coils per group (G slice stays L2-resident)

// ---------------- scratch ------------------------------------------------------
__device__ float2 g_warped[NT][NXY][NXY];      // (-1)^(x+y) * warp_t(img)   12.6 MB
__device__ float2 g_smapsT[NC][NXY][NXY];      // smaps [c][x][y]             8.4 MB
__device__ float2 g_G[GRP][NT][NXY][NXY];      // row-FFT interm, reused     50.3 MB
__device__ float2 g_outT[NC][NXY][NXY];        // result [c][ky][kx]          8.4 MB

// ---------------- complex helpers ---------------------------------------------
__device__ __forceinline__ float2 cmul(float2 a, float2 b){
    return make_float2(fmaf(a.x, b.x, -a.y*b.y), fmaf(a.x, b.y, a.y*b.x));
}
__device__ __forceinline__ float2 cadd(float2 a, float2 b){ return make_float2(a.x+b.x, a.y+b.y); }
__device__ __forceinline__ float2 csub(float2 a, float2 b){ return make_float2(a.x-b.x, a.y-b.y); }

__device__ __forceinline__ int swz2(int k){ return (k & ~7) | ((k + (k >> 3) + (k >> 6)) & 7); }

// in-register radix-8 DIF butterfly; slot j ends up holding k1 = RJ[j]
// RJ = {0,4,2,6,1,5,3,7}
__device__ __forceinline__ void radix8(float2 v[8])
{
    const float S2 = 0.70710678118654752f;
    float2 s0=cadd(v[0],v[4]), d0=csub(v[0],v[4]);
    float2 s1=cadd(v[1],v[5]), d1=csub(v[1],v[5]);
    float2 s2=cadd(v[2],v[6]), d2=csub(v[2],v[6]);
    float2 s3=cadd(v[3],v[7]), d3=csub(v[3],v[7]);
    d1 = cmul(d1, make_float2( S2,-S2));
    d2 = make_float2(d2.y, -d2.x);
    d3 = cmul(d3, make_float2(-S2,-S2));
    float2 e0=cadd(s0,s2), f0=csub(s0,s2);
    float2 e1=cadd(s1,s3), f1=csub(s1,s3);
    f1 = make_float2(f1.y, -f1.x);
    float2 e2=cadd(d0,d2), f2=csub(d0,d2);
    float2 e3=cadd(d1,d3), f3=csub(d1,d3);
    f3 = make_float2(f3.y, -f3.x);
    v[0]=cadd(e0,e1); v[1]=csub(e0,e1);
    v[2]=cadd(f0,f1); v[3]=csub(f0,f1);
    v[4]=cadd(e2,e3); v[5]=csub(e2,e3);
    v[6]=cadd(f2,f3); v[7]=csub(f2,f3);
}

// multiply slot holding k=e by wbase^e, e=1..7 — chain form (2 live regs)
__device__ __forceinline__ void twiddle_chain(float2 v[8], float2 wb)
{
    float2 w = wb;
    v[4] = cmul(v[4], w);
    w = cmul(w, wb); v[2] = cmul(v[2], w);
    w = cmul(w, wb); v[6] = cmul(v[6], w);
    w = cmul(w, wb); v[1] = cmul(v[1], w);
    w = cmul(w, wb); v[5] = cmul(v[5], w);
    w = cmul(w, wb); v[3] = cmul(v[3], w);
    w = cmul(w, wb); v[7] = cmul(v[7], w);
}

// ---------------- 256-pt FFT, chain twiddles (stage2) --------------------------
// Input : v[j] = x[32*j + L]
// Output: slot m of lane L holds X[RJ[L&7] + 8*RJ[m] + 64*rev2(L>>3)]
// scr: per-warp PRIVATE scratch, 32 rows x 10 float2 (syncwarp-protected only)
__device__ __forceinline__ void fft256_v2(float2 v[8], int L,
                                          float2* __restrict__ scr,
                                          float2 wA, float2 wB)
{
    radix8(v);
    twiddle_chain(v, wA);

    __syncwarp();
    float4* row = (float4*)(scr + L * 10);
    row[0] = make_float4(v[0].x, v[0].y, v[1].x, v[1].y);
    row[1] = make_float4(v[2].x, v[2].y, v[3].x, v[3].y);
    row[2] = make_float4(v[4].x, v[4].y, v[5].x, v[5].y);
    row[3] = make_float4(v[6].x, v[6].y, v[7].x, v[7].y);
    __syncwarp();
    const int jj = L & 7, q = L >> 3;
    const float2* col = scr + (q * 10 + jj);
    #pragma unroll
    for (int m = 0; m < 8; ++m) v[m] = col[m * 40];
    __syncwarp();

    radix8(v);
    twiddle_chain(v, wB);

    const bool hi1 = (L & 16) != 0;
    #pragma unroll
    for (int m = 0; m < 8; ++m) {
        float ox = __shfl_xor_sync(0xffffffffu, v[m].x, 16);
        float oy = __shfl_xor_sync(0xffffffffu, v[m].y, 16);
        v[m] = hi1 ? make_float2(ox - v[m].x, oy - v[m].y)
                   : make_float2(v[m].x + ox, v[m].y + oy);
    }
    if (q == 3) {
        #pragma unroll
        for (int m = 0; m < 8; ++m) v[m] = make_float2(v[m].y, -v[m].x);
    }
    const bool hi0 = (L & 8) != 0;
    #pragma unroll
    for (int m = 0; m < 8; ++m) {
        float ox = __shfl_xor_sync(0xffffffffu, v[m].x, 8);
        float oy = __shfl_xor_sync(0xffffffffu, v[m].y, 8);
        v[m] = hi0 ? make_float2(ox - v[m].x, oy - v[m].y)
                   : make_float2(v[m].x + ox, v[m].y + oy);
    }
}

// TW tables (per block, 2 KB) for the table FFT (stage3, amortized over 3 FFTs):
//   twA[k][L] = exp(-2pi i (k+1) L / 256)   k=0..6, L=0..31
//   twB[k][q] = exp(-2pi i (k+1) 8 q / 256) k=0..6, q=0..3
#define TWA_SZ (7 * 32)
#define TWB_SZ (7 * 4)
__device__ __forceinline__ void tw_setup(float2* twA, float2* twB, int tid)
{
    const float ang = -6.283185307179586f / 256.f;
    if (tid < TWA_SZ) {
        int k = tid >> 5, L = tid & 31;
        float s, c;
        __sincosf(ang * (float)((k + 1) * L), &s, &c);
        twA[tid] = make_float2(c, s);
    } else if (tid < TWA_SZ + TWB_SZ) {
        int i = tid - TWA_SZ;
        int k = i >> 2, q = i & 3;
        float s, c;
        __sincosf(ang * (float)((k + 1) * 8 * q), &s, &c);
        twB[i] = make_float2(c, s);
    }
}

// ---------------- 256-pt FFT, table twiddles (stage3) --------------------------
__device__ __forceinline__ void fft256_v3(float2 v[8], int L,
                                          float2* __restrict__ scr,
                                          const float2* __restrict__ twAL,
                                          const float2* __restrict__ twBq)
{
    radix8(v);
    v[4] = cmul(v[4], twAL[0*32]);
    v[2] = cmul(v[2], twAL[1*32]);
    v[6] = cmul(v[6], twAL[2*32]);
    v[1] = cmul(v[1], twAL[3*32]);
    v[5] = cmul(v[5], twAL[4*32]);
    v[3] = cmul(v[3], twAL[5*32]);
    v[7] = cmul(v[7], twAL[6*32]);

    __syncwarp();
    float4* row = (float4*)(scr + L * 10);
    row[0] = make_float4(v[0].x, v[0].y, v[1].x, v[1].y);
    row[1] = make_float4(v[2].x, v[2].y, v[3].x, v[3].y);
    row[2] = make_float4(v[4].x, v[4].y, v[5].x, v[5].y);
    row[3] = make_float4(v[6].x, v[6].y, v[7].x, v[7].y);
    __syncwarp();
    const int jj = L & 7, q = L >> 3;
    const float2* col = scr + (q * 10 + jj);
    #pragma unroll
    for (int m = 0; m < 8; ++m) v[m] = col[m * 40];
    __syncwarp();

    radix8(v);
    v[4] = cmul(v[4], twBq[0*4]);
    v[2] = cmul(v[2], twBq[1*4]);
    v[6] = cmul(v[6], twBq[2*4]);
    v[1] = cmul(v[1], twBq[3*4]);
    v[5] = cmul(v[5], twBq[4*4]);
    v[3] = cmul(v[3], twBq[5*4]);
    v[7] = cmul(v[7], twBq[6*4]);

    const bool hi1 = (L & 16) != 0;
    #pragma unroll
    for (int m = 0; m < 8; ++m) {
        float ox = __shfl_xor_sync(0xffffffffu, v[m].x, 16);
        float oy = __shfl_xor_sync(0xffffffffu, v[m].y, 16);
        v[m] = hi1 ? make_float2(ox - v[m].x, oy - v[m].y)
                   : make_float2(v[m].x + ox, v[m].y + oy);
    }
    if (q == 3) {
        #pragma unroll
        for (int m = 0; m < 8; ++m) v[m] = make_float2(v[m].y, -v[m].x);
    }
    const bool hi0 = (L & 8) != 0;
    #pragma unroll
    for (int m = 0; m < 8; ++m) {
        float ox = __shfl_xor_sync(0xffffffffu, v[m].x, 8);
        float oy = __shfl_xor_sync(0xffffffffu, v[m].y, 8);
        v[m] = hi0 ? make_float2(ox - v[m].x, oy - v[m].y)
                   : make_float2(v[m].x + ox, v[m].y + oy);
    }
}

__device__ __forceinline__ int rev2i(int q){ return ((q & 1) << 1) | (q >> 1); }

// ---------------- kernel 1: warp (-1)^(x+y)-folded bilinear + smaps repack -----
__global__ void __launch_bounds__(256) init_kernel(const float* __restrict__ ir,
                                                   const float* __restrict__ ii,
                                                   const float* __restrict__ flow,
                                                   const float* __restrict__ sr,
                                                   const float* __restrict__ si)
{
    const int x = blockIdx.x;
    const int y = threadIdx.x;
    if (blockIdx.y < 6) {
        const int q = blockIdx.y;                 // t-quad
        const float sgn = ((x + y) & 1) ? -1.f : 1.f;
        const float4* p = (const float4*)(flow + ((size_t)x * NXY + y) * 48);
        float4 fx4 = p[q];
        float4 fy4 = p[q + 6];
        float fxs[4] = {fx4.x, fx4.y, fx4.z, fx4.w};
        float fys[4] = {fy4.x, fy4.y, fy4.z, fy4.w};
        #pragma unroll
        for (int u = 0; u < 4; ++u) {
            int t = 4*q + u;
            float px = fminf(fmaxf((float)x + fxs[u], 0.f), 255.f);
            float py = fminf(fmaxf((float)y + fys[u], 0.f), 255.f);
            int x0 = (int)floorf(px); if (x0 > 254) x0 = 254;
            int y0 = (int)floorf(py); if (y0 > 254) y0 = 254;
            float wx = px - (float)x0, wy = py - (float)y0;
            int b = x0 * NXY + y0;
            float a0 = (1.f - wx) * (1.f - wy);
            float a1 = (1.f - wx) * wy;
            float a2 = wx * (1.f - wy);
            float a3 = wx * wy;
            float re = a0*ir[b] + a1*ir[b+1] + a2*ir[b+NXY] + a3*ir[b+NXY+1];
            float im = a0*ii[b] + a1*ii[b+1] + a2*ii[b+NXY] + a3*ii[b+NXY+1];
            g_warped[t][x][y] = make_float2(sgn * re, sgn * im);
        }
    } else {
        const int h = blockIdx.y - 6;             // coils 8h..8h+7
        const float4* pr = (const float4*)(sr + ((size_t)x * NXY + y) * NC);
        const float4* pi = (const float4*)(si + ((size_t)x * NXY + y) * NC);
        float r[8], m[8];
        #pragma unroll
        for (int q = 0; q < 2; ++q) {
            float4 a = pr[2*h + q]; r[4*q]=a.x; r[4*q+1]=a.y; r[4*q+2]=a.z; r[4*q+3]=a.w;
            float4 b = pi[2*h + q]; m[4*q]=b.x; m[4*q+1]=b.y; m[4*q+2]=b.z; m[4*q+3]=b.w;
        }
        #pragma unroll
        for (int c = 0; c < 8; ++c)
            g_smapsT[8*h + c][x][y] = make_float2(r[c], m[c]);
    }
}

// ---------------- kernel 2: row FFT along y, write transposed G ----------------
// 128 threads / 4 warps / 4 x-rows per block, 8 CTAs/SM (same 32 warps/SM but
// half-size barriers and finer CTA-level overlap). 10 KB union buffer.
__global__ void __launch_bounds__(128, 8) stage2_kernel(int c0)
{
    __shared__ float2 B[4 * 320];             // 10 KB union buffer (scr | tile)
    const int tid = threadIdx.x;
    const int warpi = tid >> 5, L = tid & 31;
    const int jj = L & 7, q = L >> 3;

    float2 wA, wB;
    {
        const float ang = -6.283185307179586f / 256.f;
        float s, c;
        __sincosf(ang * (float)L, &s, &c);
        wA = make_float2(c, s);
        // wB = exp(-2pi i * 8q/256) = wA of lane 8q — fetch via shuffle
        wB.x = __shfl_sync(0xffffffffu, wA.x, 8 * q);
        wB.y = __shfl_sync(0xffffffffu, wA.y, 8 * q);
    }

    const int xb = blockIdx.x, t = blockIdx.y, buf = blockIdx.z;
    const int c = c0 + buf;
    const int x = xb * 4 + warpi;

    const float2* wr = &g_warped[t][x][0];
    const float2* sm = &g_smapsT[c][x][0];
    float2 v[8];
    #pragma unroll
    for (int j = 0; j < 8; ++j) v[j] = cmul(wr[32*j + L], sm[32*j + L]);

    fft256_v2(v, L, B + warpi * 320, wA, wB);

    __syncthreads();                           // scr phase done (all warps)

    const int RJ[8] = {0,4,2,6,1,5,3,7};
    const int pbase = RJ[jj] + 64 * rev2i(q);
    #pragma unroll
    for (int m = 0; m < 8; ++m) {
        int pos = pbase + 8 * RJ[m];
        B[pos * 4 + ((warpi + pos + (pos >> 3) + (pos >> 6)) & 3)] = v[m];  // tile[pos][swz]
    }
    __syncthreads();

    float2* dst = &g_G[buf][t][0][xb * 4];
    #pragma unroll
    for (int i = 0; i < 8; ++i) {
        int idx = tid + i * 128;
        int ky = idx >> 2, xl = idx & 3;
        dst[(size_t)ky * NXY + xl] = B[ky * 4 + ((xl + ky + (ky >> 3) + (ky >> 6)) & 3)];
    }
}

// ---------------- kernel 3: column FFT along x + masked t-sum ------------------
// smem table twiddles amortized over 3 FFTs; mask prefetch issued first.
__global__ void __launch_bounds__(256, 4) stage3_kernel(const float* __restrict__ mask,
                                                        int c0)
{
    __shared__ float2 scr[8][320];            // 20 KB, per-warp private
    __shared__ float2 K[8][256];              // 16 KB
    __shared__ float2 twA[TWA_SZ];
    __shared__ float2 twB[TWB_SZ];

    const int tid = threadIdx.x;
    const int warpi = tid >> 5, L = tid & 31;
    const int jj = L & 7, q = L >> 3;

    tw_setup(twA, twB, tid);

    const int ky = blockIdx.x, buf = blockIdx.y;
    const int c = c0 + buf;
    const int RJ[8] = {0,4,2,6,1,5,3,7};
    const int pbase = RJ[jj] + 64 * rev2i(q);
    const int kx = tid;
    const int sx = swz2(kx);
    const float4* m4 = (const float4*)(mask + ((((size_t)kx * NXY + ky) * NC + c) * NT));

    __syncthreads();                           // tw tables ready

    float ax = 0.f, ay = 0.f;
    #pragma unroll
    for (int qq = 0; qq < 3; ++qq) {
        // prefetch mask quads first — longest-latency loads lead the pack
        float4 f0 = __ldcs(m4 + 2*qq);
        float4 f1 = __ldcs(m4 + 2*qq + 1);

        const int t = qq * 8 + warpi;
        const float2* src = &g_G[buf][t][ky][0];
        float2 v[8];
        #pragma unroll
        for (int j = 0; j < 8; ++j) v[j] = src[32*j + L];

        fft256_v3(v, L, &scr[warpi][0], twA + L, twB + q);

        if (qq) __syncthreads();               // prior K reads complete
        #pragma unroll
        for (int m = 0; m < 8; ++m)
            K[warpi][swz2(pbase + 8 * RJ[m])] = v[m];
        __syncthreads();

        float mm[8] = {f0.x, f0.y, f0.z, f0.w, f1.x, f1.y, f1.z, f1.w};
        #pragma unroll
        for (int tl = 0; tl < 8; ++tl) {
            float2 kv = K[tl][sx];
            ax = fmaf(kv.x, mm[tl], ax);
            ay = fmaf(kv.y, mm[tl], ay);
        }
    }
    const float s = ((kx + ky) & 1) ? -0.00390625f : 0.00390625f;   // (-1)^(kx+ky)/256
    g_outT[c][ky][kx] = make_float2(ax * s, ay * s);
}

// ---------------- kernel 4: repack to [2][Nx][Ny][Nc] --------------------------
__global__ void __launch_bounds__(256) final_kernel(float* __restrict__ out)
{
    const int x = blockIdx.x;
    const int y = threadIdx.x;
    const int h = blockIdx.y;
    float re[8], im[8];
    #pragma unroll
    for (int c = 0; c < 8; ++c) {
        float2 v = g_outT[8*h + c][y][x];
        re[c] = v.x; im[c] = v.y;
    }
    float* pr = out + ((size_t)x * NXY + y) * NC + 8*h;
    float* pi = pr + (size_t)NXY * NXY * NC;
    #pragma unroll
    for (int q = 0; q < 2; ++q) {
        ((float4*)pr)[q] = make_float4(re[4*q], re[4*q+1], re[4*q+2], re[4*q+3]);
        ((float4*)pi)[q] = make_float4(im[4*q], im[4*q+1], im[4*q+2], im[4*q+3]);
    }
}

// ---------------- launch -------------------------------------------------------
extern "C" void kernel_launch(void* const* d_in, const int* in_sizes, int n_in,
                              void* d_out, int out_size)
{
    (void)in_sizes; (void)n_in; (void)out_size;
    const float* image_real = (const float*)d_in[0];
    const float* image_imag = (const float*)d_in[1];
    const float* mask       = (const float*)d_in[2];
    const float* smaps_real = (const float*)d_in[3];
    const float* smaps_imag = (const float*)d_in[4];
    const float* flow       = (const float*)d_in[5];

    init_kernel<<<dim3(256, 8), 256>>>(image_real, image_imag, flow,
                                       smaps_real, smaps_imag);
    for (int c0 = 0; c0 < NC; c0 += GRP) {
        stage2_kernel<<<dim3(64, NT, GRP), 128>>>(c0);
        stage3_kernel<<<dim3(256, GRP), 256>>>(mask, c0);
    }
    final_kernel<<<dim3(256, 2), 256>>>((float*)d_out);
}

// round 16
// speedup vs baseline: 1.0430x; 1.0430x over previous
#include <cuda_runtime.h>
#include <math.h>

#define NXY 256
#define NT  24
#define NC  16
#define GRP 4      // coils per group (G slice stays L2-resident)

// ---------------- scratch ------------------------------------------------------
__device__ float2 g_warped[NT][NXY][NXY];      // (-1)^(x+y) * warp_t(img)   12.6 MB
__device__ float2 g_smapsT[NC][NXY][NXY];      // smaps [c][x][y]             8.4 MB
__device__ float2 g_G[GRP][NT][NXY][NXY];      // row-FFT interm, reused     50.3 MB
__device__ float2 g_outT[NC][NXY][NXY];        // result [c][ky][kx]          8.4 MB

// ---------------- complex helpers ---------------------------------------------
__device__ __forceinline__ float2 cmul(float2 a, float2 b){
    return make_float2(fmaf(a.x, b.x, -a.y*b.y), fmaf(a.x, b.y, a.y*b.x));
}
__device__ __forceinline__ float2 cadd(float2 a, float2 b){ return make_float2(a.x+b.x, a.y+b.y); }
__device__ __forceinline__ float2 csub(float2 a, float2 b){ return make_float2(a.x-b.x, a.y-b.y); }

__device__ __forceinline__ int swz2(int k){ return (k & ~7) | ((k + (k >> 3) + (k >> 6)) & 7); }

// in-register radix-8 DIF butterfly; slot j ends up holding k1 = RJ[j]
// RJ = {0,4,2,6,1,5,3,7}
__device__ __forceinline__ void radix8(float2 v[8])
{
    const float S2 = 0.70710678118654752f;
    float2 s0=cadd(v[0],v[4]), d0=csub(v[0],v[4]);
    float2 s1=cadd(v[1],v[5]), d1=csub(v[1],v[5]);
    float2 s2=cadd(v[2],v[6]), d2=csub(v[2],v[6]);
    float2 s3=cadd(v[3],v[7]), d3=csub(v[3],v[7]);
    d1 = cmul(d1, make_float2( S2,-S2));
    d2 = make_float2(d2.y, -d2.x);
    d3 = cmul(d3, make_float2(-S2,-S2));
    float2 e0=cadd(s0,s2), f0=csub(s0,s2);
    float2 e1=cadd(s1,s3), f1=csub(s1,s3);
    f1 = make_float2(f1.y, -f1.x);
    float2 e2=cadd(d0,d2), f2=csub(d0,d2);
    float2 e3=cadd(d1,d3), f3=csub(d1,d3);
    f3 = make_float2(f3.y, -f3.x);
    v[0]=cadd(e0,e1); v[1]=csub(e0,e1);
    v[2]=cadd(f0,f1); v[3]=csub(f0,f1);
    v[4]=cadd(e2,e3); v[5]=csub(e2,e3);
    v[6]=cadd(f2,f3); v[7]=csub(f2,f3);
}

// multiply slot holding k=e by wbase^e, e=1..7 — chain form (2 live regs)
__device__ __forceinline__ void twiddle_chain(float2 v[8], float2 wb)
{
    float2 w = wb;
    v[4] = cmul(v[4], w);
    w = cmul(w, wb); v[2] = cmul(v[2], w);
    w = cmul(w, wb); v[6] = cmul(v[6], w);
    w = cmul(w, wb); v[1] = cmul(v[1], w);
    w = cmul(w, wb); v[5] = cmul(v[5], w);
    w = cmul(w, wb); v[3] = cmul(v[3], w);
    w = cmul(w, wb); v[7] = cmul(v[7], w);
}

// ---------------- 256-pt FFT, chain twiddles (stage2) --------------------------
// Input : v[j] = x[32*j + L]
// Output: slot m of lane L holds X[RJ[L&7] + 8*RJ[m] + 64*rev2(L>>3)]
// scr: per-warp PRIVATE scratch, 32 rows x 10 float2 (syncwarp-protected only)
__device__ __forceinline__ void fft256_v2(float2 v[8], int L,
                                          float2* __restrict__ scr,
                                          float2 wA, float2 wB)
{
    radix8(v);
    twiddle_chain(v, wA);

    __syncwarp();
    float4* row = (float4*)(scr + L * 10);
    row[0] = make_float4(v[0].x, v[0].y, v[1].x, v[1].y);
    row[1] = make_float4(v[2].x, v[2].y, v[3].x, v[3].y);
    row[2] = make_float4(v[4].x, v[4].y, v[5].x, v[5].y);
    row[3] = make_float4(v[6].x, v[6].y, v[7].x, v[7].y);
    __syncwarp();
    const int jj = L & 7, q = L >> 3;
    const float2* col = scr + (q * 10 + jj);
    #pragma unroll
    for (int m = 0; m < 8; ++m) v[m] = col[m * 40];
    __syncwarp();

    radix8(v);
    twiddle_chain(v, wB);

    const bool hi1 = (L & 16) != 0;
    #pragma unroll
    for (int m = 0; m < 8; ++m) {
        float ox = __shfl_xor_sync(0xffffffffu, v[m].x, 16);
        float oy = __shfl_xor_sync(0xffffffffu, v[m].y, 16);
        v[m] = hi1 ? make_float2(ox - v[m].x, oy - v[m].y)
                   : make_float2(v[m].x + ox, v[m].y + oy);
    }
    if (q == 3) {
        #pragma unroll
        for (int m = 0; m < 8; ++m) v[m] = make_float2(v[m].y, -v[m].x);
    }
    const bool hi0 = (L & 8) != 0;
    #pragma unroll
    for (int m = 0; m < 8; ++m) {
        float ox = __shfl_xor_sync(0xffffffffu, v[m].x, 8);
        float oy = __shfl_xor_sync(0xffffffffu, v[m].y, 8);
        v[m] = hi0 ? make_float2(ox - v[m].x, oy - v[m].y)
                   : make_float2(v[m].x + ox, v[m].y + oy);
    }
}

// TW tables (per block, 2 KB) for the table FFT (stage3, amortized over 3 FFTs):
//   twA[k][L] = exp(-2pi i (k+1) L / 256)   k=0..6, L=0..31
//   twB[k][q] = exp(-2pi i (k+1) 8 q / 256) k=0..6, q=0..3
#define TWA_SZ (7 * 32)
#define TWB_SZ (7 * 4)
__device__ __forceinline__ void tw_setup(float2* twA, float2* twB, int tid)
{
    const float ang = -6.283185307179586f / 256.f;
    if (tid < TWA_SZ) {
        int k = tid >> 5, L = tid & 31;
        float s, c;
        __sincosf(ang * (float)((k + 1) * L), &s, &c);
        twA[tid] = make_float2(c, s);
    } else if (tid < TWA_SZ + TWB_SZ) {
        int i = tid - TWA_SZ;
        int k = i >> 2, q = i & 3;
        float s, c;
        __sincosf(ang * (float)((k + 1) * 8 * q), &s, &c);
        twB[i] = make_float2(c, s);
    }
}

// ---------------- 256-pt FFT, table twiddles (stage3) --------------------------
__device__ __forceinline__ void fft256_v3(float2 v[8], int L,
                                          float2* __restrict__ scr,
                                          const float2* __restrict__ twAL,
                                          const float2* __restrict__ twBq)
{
    radix8(v);
    v[4] = cmul(v[4], twAL[0*32]);
    v[2] = cmul(v[2], twAL[1*32]);
    v[6] = cmul(v[6], twAL[2*32]);
    v[1] = cmul(v[1], twAL[3*32]);
    v[5] = cmul(v[5], twAL[4*32]);
    v[3] = cmul(v[3], twAL[5*32]);
    v[7] = cmul(v[7], twAL[6*32]);

    __syncwarp();
    float4* row = (float4*)(scr + L * 10);
    row[0] = make_float4(v[0].x, v[0].y, v[1].x, v[1].y);
    row[1] = make_float4(v[2].x, v[2].y, v[3].x, v[3].y);
    row[2] = make_float4(v[4].x, v[4].y, v[5].x, v[5].y);
    row[3] = make_float4(v[6].x, v[6].y, v[7].x, v[7].y);
    __syncwarp();
    const int jj = L & 7, q = L >> 3;
    const float2* col = scr + (q * 10 + jj);
    #pragma unroll
    for (int m = 0; m < 8; ++m) v[m] = col[m * 40];
    __syncwarp();

    radix8(v);
    v[4] = cmul(v[4], twBq[0*4]);
    v[2] = cmul(v[2], twBq[1*4]);
    v[6] = cmul(v[6], twBq[2*4]);
    v[1] = cmul(v[1], twBq[3*4]);
    v[5] = cmul(v[5], twBq[4*4]);
    v[3] = cmul(v[3], twBq[5*4]);
    v[7] = cmul(v[7], twBq[6*4]);

    const bool hi1 = (L & 16) != 0;
    #pragma unroll
    for (int m = 0; m < 8; ++m) {
        float ox = __shfl_xor_sync(0xffffffffu, v[m].x, 16);
        float oy = __shfl_xor_sync(0xffffffffu, v[m].y, 16);
        v[m] = hi1 ? make_float2(ox - v[m].x, oy - v[m].y)
                   : make_float2(v[m].x + ox, v[m].y + oy);
    }
    if (q == 3) {
        #pragma unroll
        for (int m = 0; m < 8; ++m) v[m] = make_float2(v[m].y, -v[m].x);
    }
    const bool hi0 = (L & 8) != 0;
    #pragma unroll
    for (int m = 0; m < 8; ++m) {
        float ox = __shfl_xor_sync(0xffffffffu, v[m].x, 8);
        float oy = __shfl_xor_sync(0xffffffffu, v[m].y, 8);
        v[m] = hi0 ? make_float2(ox - v[m].x, oy - v[m].y)
                   : make_float2(v[m].x + ox, v[m].y + oy);
    }
}

__device__ __forceinline__ int rev2i(int q){ return ((q & 1) << 1) | (q >> 1); }

// ---------------- kernel 1: warp (-1)^(x+y)-folded bilinear + smaps repack -----
__global__ void __launch_bounds__(256) init_kernel(const float* __restrict__ ir,
                                                   const float* __restrict__ ii,
                                                   const float* __restrict__ flow,
                                                   const float* __restrict__ sr,
                                                   const float* __restrict__ si)
{
    const int x = blockIdx.x;
    const int y = threadIdx.x;
    if (blockIdx.y < 6) {
        const int q = blockIdx.y;                 // t-quad
        const float sgn = ((x + y) & 1) ? -1.f : 1.f;
        const float4* p = (const float4*)(flow + ((size_t)x * NXY + y) * 48);
        float4 fx4 = p[q];
        float4 fy4 = p[q + 6];
        float fxs[4] = {fx4.x, fx4.y, fx4.z, fx4.w};
        float fys[4] = {fy4.x, fy4.y, fy4.z, fy4.w};
        #pragma unroll
        for (int u = 0; u < 4; ++u) {
            int t = 4*q + u;
            float px = fminf(fmaxf((float)x + fxs[u], 0.f), 255.f);
            float py = fminf(fmaxf((float)y + fys[u], 0.f), 255.f);
            int x0 = (int)floorf(px); if (x0 > 254) x0 = 254;
            int y0 = (int)floorf(py); if (y0 > 254) y0 = 254;
            float wx = px - (float)x0, wy = py - (float)y0;
            int b = x0 * NXY + y0;
            float a0 = (1.f - wx) * (1.f - wy);
            float a1 = (1.f - wx) * wy;
            float a2 = wx * (1.f - wy);
            float a3 = wx * wy;
            float re = a0*ir[b] + a1*ir[b+1] + a2*ir[b+NXY] + a3*ir[b+NXY+1];
            float im = a0*ii[b] + a1*ii[b+1] + a2*ii[b+NXY] + a3*ii[b+NXY+1];
            g_warped[t][x][y] = make_float2(sgn * re, sgn * im);
        }
    } else {
        const int h = blockIdx.y - 6;             // coils 8h..8h+7
        const float4* pr = (const float4*)(sr + ((size_t)x * NXY + y) * NC);
        const float4* pi = (const float4*)(si + ((size_t)x * NXY + y) * NC);
        float r[8], m[8];
        #pragma unroll
        for (int q = 0; q < 2; ++q) {
            float4 a = pr[2*h + q]; r[4*q]=a.x; r[4*q+1]=a.y; r[4*q+2]=a.z; r[4*q+3]=a.w;
            float4 b = pi[2*h + q]; m[4*q]=b.x; m[4*q+1]=b.y; m[4*q+2]=b.z; m[4*q+3]=b.w;
        }
        #pragma unroll
        for (int c = 0; c < 8; ++c)
            g_smapsT[8*h + c][x][y] = make_float2(r[c], m[c]);
    }
}

// ---------------- kernel 2: row FFT along y, write transposed G ----------------
// 20 KB union buffer (scr aliases tile, separated by __syncthreads()).
__global__ void __launch_bounds__(256, 4) stage2_kernel(int c0)
{
    __shared__ float2 B[8 * 320];             // 20 KB union buffer
    const int tid = threadIdx.x;
    const int warpi = tid >> 5, L = tid & 31;
    const int jj = L & 7, q = L >> 3;

    float2 wA, wB;
    {
        const float ang = -6.283185307179586f / 256.f;
        float s, c;
        __sincosf(ang * (float)L, &s, &c);        wA = make_float2(c, s);
        __sincosf(ang * (float)(8 * q), &s, &c);  wB = make_float2(c, s);
    }

    const int xb = blockIdx.x, t = blockIdx.y, buf = blockIdx.z;
    const int c = c0 + buf;
    const int x = xb * 8 + warpi;

    const float2* wr = &g_warped[t][x][0];
    const float2* sm = &g_smapsT[c][x][0];
    float2 v[8];
    #pragma unroll
    for (int j = 0; j < 8; ++j) v[j] = cmul(wr[32*j + L], sm[32*j + L]);

    fft256_v2(v, L, B + warpi * 320, wA, wB);

    __syncthreads();                           // scr phase done (all warps)

    const int RJ[8] = {0,4,2,6,1,5,3,7};
    const int pbase = RJ[jj] + 64 * rev2i(q);
    #pragma unroll
    for (int m = 0; m < 8; ++m) {
        int pos = pbase + 8 * RJ[m];
        B[pos * 8 + ((warpi + pos + (pos >> 3)) & 7)] = v[m];   // tile[pos][swz]
    }
    __syncthreads();

    float2* dst = &g_G[buf][t][0][xb * 8];
    #pragma unroll
    for (int i = 0; i < 8; ++i) {
        int idx = tid + i * 256;
        int ky = idx >> 3, xl = idx & 7;
        dst[(size_t)ky * NXY + xl] = B[ky * 8 + ((xl + ky + (ky >> 3)) & 7)];
    }
}

// ---------------- kernel 3: column FFT along x + masked t-sum ------------------
// smem table twiddles amortized over 3 FFTs; mask prefetched before the FFT.
__global__ void __launch_bounds__(256, 4) stage3_kernel(const float* __restrict__ mask,
                                                        int c0)
{
    __shared__ float2 scr[8][320];            // 20 KB, per-warp private
    __shared__ float2 K[8][256];              // 16 KB
    __shared__ float2 twA[TWA_SZ];
    __shared__ float2 twB[TWB_SZ];

    const int tid = threadIdx.x;
    const int warpi = tid >> 5, L = tid & 31;
    const int jj = L & 7, q = L >> 3;

    tw_setup(twA, twB, tid);

    const int ky = blockIdx.x, buf = blockIdx.y;
    const int c = c0 + buf;
    const int RJ[8] = {0,4,2,6,1,5,3,7};
    const int pbase = RJ[jj] + 64 * rev2i(q);
    const int kx = tid;
    const int sx = swz2(kx);
    const float4* m4 = (const float4*)(mask + ((((size_t)kx * NXY + ky) * NC + c) * NT));

    __syncthreads();                           // tw tables ready

    float ax = 0.f, ay = 0.f;
    #pragma unroll
    for (int qq = 0; qq < 3; ++qq) {
        const int t = qq * 8 + warpi;
        const float2* src = &g_G[buf][t][ky][0];
        float2 v[8];
        #pragma unroll
        for (int j = 0; j < 8; ++j) v[j] = src[32*j + L];

        // prefetch this iteration's mask quads — consumed after the FFT+barrier
        float4 f0 = __ldcs(m4 + 2*qq);
        float4 f1 = __ldcs(m4 + 2*qq + 1);

        fft256_v3(v, L, &scr[warpi][0], twA + L, twB + q);

        if (qq) __syncthreads();               // prior K reads complete
        #pragma unroll
        for (int m = 0; m < 8; ++m)
            K[warpi][swz2(pbase + 8 * RJ[m])] = v[m];
        __syncthreads();

        float mm[8] = {f0.x, f0.y, f0.z, f0.w, f1.x, f1.y, f1.z, f1.w};
        #pragma unroll
        for (int tl = 0; tl < 8; ++tl) {
            float2 kv = K[tl][sx];
            ax = fmaf(kv.x, mm[tl], ax);
            ay = fmaf(kv.y, mm[tl], ay);
        }
    }
    const float s = ((kx + ky) & 1) ? -0.00390625f : 0.00390625f;   // (-1)^(kx+ky)/256
    g_outT[c][ky][kx] = make_float2(ax * s, ay * s);
}

// ---------------- kernel 4: repack to [2][Nx][Ny][Nc] --------------------------
__global__ void __launch_bounds__(256) final_kernel(float* __restrict__ out)
{
    const int x = blockIdx.x;
    const int y = threadIdx.x;
    const int h = blockIdx.y;
    float re[8], im[8];
    #pragma unroll
    for (int c = 0; c < 8; ++c) {
        float2 v = g_outT[8*h + c][y][x];
        re[c] = v.x; im[c] = v.y;
    }
    float* pr = out + ((size_t)x * NXY + y) * NC + 8*h;
    float* pi = pr + (size_t)NXY * NXY * NC;
    #pragma unroll
    for (int q = 0; q < 2; ++q) {
        ((float4*)pr)[q] = make_float4(re[4*q], re[4*q+1], re[4*q+2], re[4*q+3]);
        ((float4*)pi)[q] = make_float4(im[4*q], im[4*q+1], im[4*q+2], im[4*q+3]);
    }
}

// ---------------- launch -------------------------------------------------------
extern "C" void kernel_launch(void* const* d_in, const int* in_sizes, int n_in,
                              void* d_out, int out_size)
{
    (void)in_sizes; (void)n_in; (void)out_size;
    const float* image_real = (const float*)d_in[0];
    const float* image_imag = (const float*)d_in[1];
    const float* mask       = (const float*)d_in[2];
    const float* smaps_real = (const float*)d_in[3];
    const float* smaps_imag = (const float*)d_in[4];
    const float* flow       = (const float*)d_in[5];

    init_kernel<<<dim3(256, 8), 256>>>(image_real, image_imag, flow,
                                       smaps_real, smaps_imag);
    for (int c0 = 0; c0 < NC; c0 += GRP) {
        stage2_kernel<<<dim3(32, NT, GRP), 256>>>(c0);
        stage3_kernel<<<dim3(256, GRP), 256>>>(mask, c0);
    }
    final_kernel<<<dim3(256, 2), 256>>>((float*)d_out);
}